// round 1
// baseline (speedup 1.0000x reference)
#include <cuda_runtime.h>

#define SEQ  8192
#define DIN  512
#define DOUT 64

#define BM   128      // query rows per attention block
#define BN   128      // keys per tile
#define KSTR 68       // padded K-tile row stride (floats)
#define PSTR 132      // padded P-tile row stride (floats)
#define HALFK (SEQ/2) // keys per split-K half
#define NT   (HALFK/BN)

// -------- device scratch (no allocations allowed) --------
__device__ float g_Q[SEQ*DOUT];
__device__ float g_K[SEQ*DOUT];
__device__ float g_V[SEQ*DOUT];
__device__ float g_Op[2][SEQ*DOUT];
__device__ float g_m[2][SEQ];
__device__ float g_l[2][SEQ];

// -------- fast exp on the FMA pipe (avoid MUFU throughput wall) --------
// exp(x) for x <= 0.  ~3e-6 relative error. ~10 ops, no MUFU.
__device__ __forceinline__ float fexp(float x) {
    x = fmaxf(x, -87.0f);
    float y = x * 1.4426950408889634f;   // x * log2(e)
    float r = rintf(y);
    float f = y - r;                     // f in [-0.5, 0.5]
    float p =             1.5403530393e-4f;
    p = fmaf(p, f, 1.3333558146e-3f);
    p = fmaf(p, f, 9.6181291076e-3f);
    p = fmaf(p, f, 5.5504108665e-2f);
    p = fmaf(p, f, 2.4022650696e-1f);
    p = fmaf(p, f, 6.9314718056e-1f);
    p = fmaf(p, f, 1.0f);                // 2^f
    int e = (int)r;                      // e in [-126, 0]
    return p * __int_as_float((e + 127) << 23);
}

// ============================================================
// Projection: out = x @ W  (M=8192, N=64, K=512), 3 W's via gridDim.y.
// Q gets the 1/sqrt(64) softmax scale folded in.
// ============================================================
__global__ __launch_bounds__(256) void proj_kernel(
    const float* __restrict__ x,  const float* __restrict__ Wq,
    const float* __restrict__ Wk, const float* __restrict__ Wv)
{
    __shared__ float xs[64*64];
    __shared__ float ws[64*64];

    const int which = blockIdx.y;
    const float* W  = (which == 0) ? Wq : ((which == 1) ? Wk : Wv);
    float* out      = (which == 0) ? g_Q : ((which == 1) ? g_K : g_V);
    const float scale = (which == 0) ? 0.125f : 1.0f;

    const int row0 = blockIdx.x * 64;
    const int tx = threadIdx.x, ty = threadIdx.y;
    const int tid = ty * 16 + tx;

    float acc[4][4];
#pragma unroll
    for (int i = 0; i < 4; i++)
#pragma unroll
        for (int j = 0; j < 4; j++) acc[i][j] = 0.0f;

    for (int kt = 0; kt < 8; kt++) {
#pragma unroll
        for (int i = 0; i < 4; i++) {
            int lin = tid + 256 * i;
            int r = lin >> 4, c = (lin & 15) * 4;
            *(float4*)&xs[r*64 + c] = *(const float4*)&x[(row0 + r)*DIN + kt*64 + c];
            *(float4*)&ws[r*64 + c] = *(const float4*)&W[(kt*64 + r)*DOUT + c];
        }
        __syncthreads();
#pragma unroll 4
        for (int k = 0; k < 64; k += 4) {
            float4 a[4], b[4];
#pragma unroll
            for (int i = 0; i < 4; i++) a[i] = *(float4*)&xs[(ty*4 + i)*64 + k];
#pragma unroll
            for (int t = 0; t < 4; t++) b[t] = *(float4*)&ws[(k + t)*64 + tx*4];
#pragma unroll
            for (int i = 0; i < 4; i++) {
                acc[i][0] = fmaf(a[i].x,b[0].x, fmaf(a[i].y,b[1].x, fmaf(a[i].z,b[2].x, fmaf(a[i].w,b[3].x, acc[i][0]))));
                acc[i][1] = fmaf(a[i].x,b[0].y, fmaf(a[i].y,b[1].y, fmaf(a[i].z,b[2].y, fmaf(a[i].w,b[3].y, acc[i][1]))));
                acc[i][2] = fmaf(a[i].x,b[0].z, fmaf(a[i].y,b[1].z, fmaf(a[i].z,b[2].z, fmaf(a[i].w,b[3].z, acc[i][2]))));
                acc[i][3] = fmaf(a[i].x,b[0].w, fmaf(a[i].y,b[1].w, fmaf(a[i].z,b[2].w, fmaf(a[i].w,b[3].w, acc[i][3]))));
            }
        }
        __syncthreads();
    }
#pragma unroll
    for (int i = 0; i < 4; i++) {
        float4 v;
        v.x = acc[i][0]*scale; v.y = acc[i][1]*scale;
        v.z = acc[i][2]*scale; v.w = acc[i][3]*scale;
        *(float4*)&out[(row0 + ty*4 + i)*DOUT + tx*4] = v;
    }
}

// ============================================================
// Flash attention, split-K over 2 key halves. 256 thr, 8x8 micro-tile.
// Writes unnormalized O plus per-row (m, l) partials.
// ============================================================
__global__ __launch_bounds__(256) void attn_kernel()
{
    extern __shared__ float sm[];
    float* Qs = sm;                 // [BM][64]
    float* Ks = Qs + BM*64;         // [BN][KSTR]
    float* Vs = Ks + BN*KSTR;       // [BN][64]
    float* Ps = Vs + BN*64;         // [BM][PSTR]

    const int tx = threadIdx.x, ty = threadIdx.y;
    const int tid = ty * 16 + tx;
    const int row0 = blockIdx.x * BM;
    const int half = blockIdx.y;

    // load Q tile (already scaled by 1/8)
#pragma unroll
    for (int i = 0; i < 8; i++) {
        int lin = tid + 256 * i;
        int r = lin >> 4, c = (lin & 15) * 4;
        *(float4*)&Qs[r*64 + c] = *(const float4*)&g_Q[(row0 + r)*DOUT + c];
    }

    float m[8], l[8], O[8][4];
#pragma unroll
    for (int i = 0; i < 8; i++) {
        m[i] = -1e30f; l[i] = 0.0f;
#pragma unroll
        for (int j = 0; j < 4; j++) O[i][j] = 0.0f;
    }

    for (int t = 0; t < NT; t++) {
        const int kb = half * HALFK + t * BN;
        __syncthreads();   // prev-iter P/V reads done (and Q store visible on t=0)
#pragma unroll
        for (int i = 0; i < 8; i++) {
            int lin = tid + 256 * i;
            int r = lin >> 4, c = (lin & 15) * 4;
            *(float4*)&Ks[r*KSTR + c] = *(const float4*)&g_K[(kb + r)*DOUT + c];
            *(float4*)&Vs[r*64  + c] = *(const float4*)&g_V[(kb + r)*DOUT + c];
        }
        __syncthreads();

        // ---- S = Q @ K^T ----
        float s[8][8];
#pragma unroll
        for (int i = 0; i < 8; i++)
#pragma unroll
            for (int j = 0; j < 8; j++) s[i][j] = 0.0f;

#pragma unroll 2
        for (int d = 0; d < 64; d += 4) {
            float4 qv[8];
#pragma unroll
            for (int i = 0; i < 8; i++) qv[i] = *(float4*)&Qs[(ty*8 + i)*64 + d];
#pragma unroll
            for (int j = 0; j < 8; j++) {
                float4 kv = *(float4*)&Ks[(tx + j*16)*KSTR + d];
#pragma unroll
                for (int i = 0; i < 8; i++) {
                    s[i][j] = fmaf(qv[i].x, kv.x, s[i][j]);
                    s[i][j] = fmaf(qv[i].y, kv.y, s[i][j]);
                    s[i][j] = fmaf(qv[i].z, kv.z, s[i][j]);
                    s[i][j] = fmaf(qv[i].w, kv.w, s[i][j]);
                }
            }
        }

        // ---- online softmax (row stats across the 16 tx lanes) ----
#pragma unroll
        for (int i = 0; i < 8; i++) {
            float rm = s[i][0];
#pragma unroll
            for (int j = 1; j < 8; j++) rm = fmaxf(rm, s[i][j]);
            rm = fmaxf(rm, __shfl_xor_sync(0xFFFFFFFFu, rm, 1, 16));
            rm = fmaxf(rm, __shfl_xor_sync(0xFFFFFFFFu, rm, 2, 16));
            rm = fmaxf(rm, __shfl_xor_sync(0xFFFFFFFFu, rm, 4, 16));
            rm = fmaxf(rm, __shfl_xor_sync(0xFFFFFFFFu, rm, 8, 16));
            float mn = fmaxf(m[i], rm);
            float alpha = fexp(m[i] - mn);
            m[i] = mn;
            float rs = 0.0f;
#pragma unroll
            for (int j = 0; j < 8; j++) {
                float p = fexp(s[i][j] - mn);
                s[i][j] = p;
                rs += p;
            }
            rs += __shfl_xor_sync(0xFFFFFFFFu, rs, 1, 16);
            rs += __shfl_xor_sync(0xFFFFFFFFu, rs, 2, 16);
            rs += __shfl_xor_sync(0xFFFFFFFFu, rs, 4, 16);
            rs += __shfl_xor_sync(0xFFFFFFFFu, rs, 8, 16);
            l[i] = l[i] * alpha + rs;
#pragma unroll
            for (int j = 0; j < 4; j++) O[i][j] *= alpha;
#pragma unroll
            for (int j = 0; j < 8; j++) Ps[(ty*8 + i)*PSTR + tx + j*16] = s[i][j];
        }
        __syncthreads();

        // ---- O += P @ V ----
#pragma unroll 2
        for (int kk = 0; kk < BN; kk += 4) {
            float4 pv[8];
#pragma unroll
            for (int i = 0; i < 8; i++) pv[i] = *(float4*)&Ps[(ty*8 + i)*PSTR + kk];
            float vv[4][4];
#pragma unroll
            for (int t4 = 0; t4 < 4; t4++)
#pragma unroll
                for (int j = 0; j < 4; j++) vv[t4][j] = Vs[(kk + t4)*64 + tx + j*16];
#pragma unroll
            for (int i = 0; i < 8; i++)
#pragma unroll
                for (int j = 0; j < 4; j++) {
                    O[i][j] = fmaf(pv[i].x, vv[0][j], O[i][j]);
                    O[i][j] = fmaf(pv[i].y, vv[1][j], O[i][j]);
                    O[i][j] = fmaf(pv[i].z, vv[2][j], O[i][j]);
                    O[i][j] = fmaf(pv[i].w, vv[3][j], O[i][j]);
                }
        }
    }

    // epilogue: unnormalized partials
#pragma unroll
    for (int i = 0; i < 8; i++) {
        int row = row0 + ty*8 + i;
        if (tx == 0) { g_m[half][row] = m[i]; g_l[half][row] = l[i]; }
#pragma unroll
        for (int j = 0; j < 4; j++)
            g_Op[half][row*DOUT + tx + j*16] = O[i][j];
    }
}

// ============================================================
// Combine the two split-K partials.
// ============================================================
__global__ __launch_bounds__(256) void combine_kernel(float* __restrict__ out)
{
    int idx = blockIdx.x * 256 + threadIdx.x;
    int row = idx >> 6;
    float m0 = g_m[0][row], m1 = g_m[1][row];
    float mx = fmaxf(m0, m1);
    float a0 = __expf(m0 - mx);
    float a1 = __expf(m1 - mx);
    float denom = g_l[0][row]*a0 + g_l[1][row]*a1;
    out[idx] = (g_Op[0][idx]*a0 + g_Op[1][idx]*a1) / denom;
}

// ============================================================
extern "C" void kernel_launch(void* const* d_in, const int* in_sizes, int n_in,
                              void* d_out, int out_size)
{
    const float* x  = (const float*)d_in[0];
    const float* Wq = (const float*)d_in[1];
    const float* Wk = (const float*)d_in[2];
    const float* Wv = (const float*)d_in[3];
    float* out = (float*)d_out;

    const int attn_smem = (BM*64 + BN*KSTR + BN*64 + BM*PSTR) * (int)sizeof(float);
    cudaFuncSetAttribute(attn_kernel, cudaFuncAttributeMaxDynamicSharedMemorySize, attn_smem);

    proj_kernel<<<dim3(SEQ/64, 3), dim3(16, 16)>>>(x, Wq, Wk, Wv);
    attn_kernel<<<dim3(SEQ/BM, 2), dim3(16, 16), attn_smem>>>();
    combine_kernel<<<(SEQ*DOUT)/256, 256>>>(out);
}

// round 2
// speedup vs baseline: 1.0028x; 1.0028x over previous
#include <cuda_runtime.h>

#define SEQ  8192
#define DIN  512
#define DOUT 64

#define BM   128      // query rows per attention block
#define BN   128      // keys per tile
#define KSTR 68       // padded K-tile row stride (floats)
#define PSTR 132      // padded P-tile row stride (floats)
#define HALFK (SEQ/2) // keys per split-K half
#define NT   (HALFK/BN)

// -------- device scratch (no allocations allowed) --------
__device__ float g_Q[SEQ*DOUT];
__device__ float g_K[SEQ*DOUT];
__device__ float g_V[SEQ*DOUT];
__device__ float g_Op[2][SEQ*DOUT];
__device__ float g_m[2][SEQ];
__device__ float g_l[2][SEQ];

// -------- fast exp on the FMA pipe (avoid MUFU throughput wall) --------
// exp(x) for x <= 0.  ~3e-6 relative error. ~10 ops, no MUFU.
__device__ __forceinline__ float fexp(float x) {
    x = fmaxf(x, -87.0f);
    float y = x * 1.4426950408889634f;   // x * log2(e)
    float r = rintf(y);
    float f = y - r;                     // f in [-0.5, 0.5]
    float p =             1.5403530393e-4f;
    p = fmaf(p, f, 1.3333558146e-3f);
    p = fmaf(p, f, 9.6181291076e-3f);
    p = fmaf(p, f, 5.5504108665e-2f);
    p = fmaf(p, f, 2.4022650696e-1f);
    p = fmaf(p, f, 6.9314718056e-1f);
    p = fmaf(p, f, 1.0f);                // 2^f
    int e = (int)r;                      // e in [-126, 0]
    return p * __int_as_float((e + 127) << 23);
}

// ============================================================
// Projection: out = x @ W  (M=8192, N=64, K=512), 3 W's via gridDim.y.
// Q gets the 1/sqrt(64) softmax scale folded in.
// ============================================================
__global__ __launch_bounds__(256) void proj_kernel(
    const float* __restrict__ x,  const float* __restrict__ Wq,
    const float* __restrict__ Wk, const float* __restrict__ Wv)
{
    __shared__ float xs[64*64];
    __shared__ float ws[64*64];

    const int which = blockIdx.y;
    const float* W  = (which == 0) ? Wq : ((which == 1) ? Wk : Wv);
    float* out      = (which == 0) ? g_Q : ((which == 1) ? g_K : g_V);
    const float scale = (which == 0) ? 0.125f : 1.0f;

    const int row0 = blockIdx.x * 64;
    const int tx = threadIdx.x, ty = threadIdx.y;
    const int tid = ty * 16 + tx;

    float acc[4][4];
#pragma unroll
    for (int i = 0; i < 4; i++)
#pragma unroll
        for (int j = 0; j < 4; j++) acc[i][j] = 0.0f;

    for (int kt = 0; kt < 8; kt++) {
#pragma unroll
        for (int i = 0; i < 4; i++) {
            int lin = tid + 256 * i;
            int r = lin >> 4, c = (lin & 15) * 4;
            *(float4*)&xs[r*64 + c] = *(const float4*)&x[(row0 + r)*DIN + kt*64 + c];
            *(float4*)&ws[r*64 + c] = *(const float4*)&W[(kt*64 + r)*DOUT + c];
        }
        __syncthreads();
#pragma unroll 4
        for (int k = 0; k < 64; k += 4) {
            float4 a[4], b[4];
#pragma unroll
            for (int i = 0; i < 4; i++) a[i] = *(float4*)&xs[(ty*4 + i)*64 + k];
#pragma unroll
            for (int t = 0; t < 4; t++) b[t] = *(float4*)&ws[(k + t)*64 + tx*4];
#pragma unroll
            for (int i = 0; i < 4; i++) {
                acc[i][0] = fmaf(a[i].x,b[0].x, fmaf(a[i].y,b[1].x, fmaf(a[i].z,b[2].x, fmaf(a[i].w,b[3].x, acc[i][0]))));
                acc[i][1] = fmaf(a[i].x,b[0].y, fmaf(a[i].y,b[1].y, fmaf(a[i].z,b[2].y, fmaf(a[i].w,b[3].y, acc[i][1]))));
                acc[i][2] = fmaf(a[i].x,b[0].z, fmaf(a[i].y,b[1].z, fmaf(a[i].z,b[2].z, fmaf(a[i].w,b[3].z, acc[i][2]))));
                acc[i][3] = fmaf(a[i].x,b[0].w, fmaf(a[i].y,b[1].w, fmaf(a[i].z,b[2].w, fmaf(a[i].w,b[3].w, acc[i][3]))));
            }
        }
        __syncthreads();
    }
#pragma unroll
    for (int i = 0; i < 4; i++) {
        float4 v;
        v.x = acc[i][0]*scale; v.y = acc[i][1]*scale;
        v.z = acc[i][2]*scale; v.w = acc[i][3]*scale;
        *(float4*)&out[(row0 + ty*4 + i)*DOUT + tx*4] = v;
    }
}

// ============================================================
// Flash attention, split-K over 2 key halves. 256 thr, 8x8 micro-tile.
// Writes unnormalized O plus per-row (m, l) partials.
// ============================================================
__global__ __launch_bounds__(256) void attn_kernel()
{
    extern __shared__ float sm[];
    float* Qs = sm;                 // [BM][64]
    float* Ks = Qs + BM*64;         // [BN][KSTR]
    float* Vs = Ks + BN*KSTR;       // [BN][64]
    float* Ps = Vs + BN*64;         // [BM][PSTR]

    const int tx = threadIdx.x, ty = threadIdx.y;
    const int tid = ty * 16 + tx;
    const int row0 = blockIdx.x * BM;
    const int half = blockIdx.y;

    // load Q tile (already scaled by 1/8)
#pragma unroll
    for (int i = 0; i < 8; i++) {
        int lin = tid + 256 * i;
        int r = lin >> 4, c = (lin & 15) * 4;
        *(float4*)&Qs[r*64 + c] = *(const float4*)&g_Q[(row0 + r)*DOUT + c];
    }

    float m[8], l[8], O[8][4];
#pragma unroll
    for (int i = 0; i < 8; i++) {
        m[i] = -1e30f; l[i] = 0.0f;
#pragma unroll
        for (int j = 0; j < 4; j++) O[i][j] = 0.0f;
    }

    for (int t = 0; t < NT; t++) {
        const int kb = half * HALFK + t * BN;
        __syncthreads();   // prev-iter P/V reads done (and Q store visible on t=0)
#pragma unroll
        for (int i = 0; i < 8; i++) {
            int lin = tid + 256 * i;
            int r = lin >> 4, c = (lin & 15) * 4;
            *(float4*)&Ks[r*KSTR + c] = *(const float4*)&g_K[(kb + r)*DOUT + c];
            *(float4*)&Vs[r*64  + c] = *(const float4*)&g_V[(kb + r)*DOUT + c];
        }
        __syncthreads();

        // ---- S = Q @ K^T ----
        float s[8][8];
#pragma unroll
        for (int i = 0; i < 8; i++)
#pragma unroll
            for (int j = 0; j < 8; j++) s[i][j] = 0.0f;

#pragma unroll 2
        for (int d = 0; d < 64; d += 4) {
            float4 qv[8];
#pragma unroll
            for (int i = 0; i < 8; i++) qv[i] = *(float4*)&Qs[(ty*8 + i)*64 + d];
#pragma unroll
            for (int j = 0; j < 8; j++) {
                float4 kv = *(float4*)&Ks[(tx + j*16)*KSTR + d];
#pragma unroll
                for (int i = 0; i < 8; i++) {
                    s[i][j] = fmaf(qv[i].x, kv.x, s[i][j]);
                    s[i][j] = fmaf(qv[i].y, kv.y, s[i][j]);
                    s[i][j] = fmaf(qv[i].z, kv.z, s[i][j]);
                    s[i][j] = fmaf(qv[i].w, kv.w, s[i][j]);
                }
            }
        }

        // ---- online softmax (row stats across the 16 tx lanes) ----
#pragma unroll
        for (int i = 0; i < 8; i++) {
            float rm = s[i][0];
#pragma unroll
            for (int j = 1; j < 8; j++) rm = fmaxf(rm, s[i][j]);
            rm = fmaxf(rm, __shfl_xor_sync(0xFFFFFFFFu, rm, 1, 16));
            rm = fmaxf(rm, __shfl_xor_sync(0xFFFFFFFFu, rm, 2, 16));
            rm = fmaxf(rm, __shfl_xor_sync(0xFFFFFFFFu, rm, 4, 16));
            rm = fmaxf(rm, __shfl_xor_sync(0xFFFFFFFFu, rm, 8, 16));
            float mn = fmaxf(m[i], rm);
            float alpha = fexp(m[i] - mn);
            m[i] = mn;
            float rs = 0.0f;
#pragma unroll
            for (int j = 0; j < 8; j++) {
                float p = fexp(s[i][j] - mn);
                s[i][j] = p;
                rs += p;
            }
            rs += __shfl_xor_sync(0xFFFFFFFFu, rs, 1, 16);
            rs += __shfl_xor_sync(0xFFFFFFFFu, rs, 2, 16);
            rs += __shfl_xor_sync(0xFFFFFFFFu, rs, 4, 16);
            rs += __shfl_xor_sync(0xFFFFFFFFu, rs, 8, 16);
            l[i] = l[i] * alpha + rs;
#pragma unroll
            for (int j = 0; j < 4; j++) O[i][j] *= alpha;
#pragma unroll
            for (int j = 0; j < 8; j++) Ps[(ty*8 + i)*PSTR + tx + j*16] = s[i][j];
        }
        __syncthreads();

        // ---- O += P @ V ----
#pragma unroll 2
        for (int kk = 0; kk < BN; kk += 4) {
            float4 pv[8];
#pragma unroll
            for (int i = 0; i < 8; i++) pv[i] = *(float4*)&Ps[(ty*8 + i)*PSTR + kk];
            float vv[4][4];
#pragma unroll
            for (int t4 = 0; t4 < 4; t4++)
#pragma unroll
                for (int j = 0; j < 4; j++) vv[t4][j] = Vs[(kk + t4)*64 + tx + j*16];
#pragma unroll
            for (int i = 0; i < 8; i++)
#pragma unroll
                for (int j = 0; j < 4; j++) {
                    O[i][j] = fmaf(pv[i].x, vv[0][j], O[i][j]);
                    O[i][j] = fmaf(pv[i].y, vv[1][j], O[i][j]);
                    O[i][j] = fmaf(pv[i].z, vv[2][j], O[i][j]);
                    O[i][j] = fmaf(pv[i].w, vv[3][j], O[i][j]);
                }
        }
    }

    // epilogue: unnormalized partials
#pragma unroll
    for (int i = 0; i < 8; i++) {
        int row = row0 + ty*8 + i;
        if (tx == 0) { g_m[half][row] = m[i]; g_l[half][row] = l[i]; }
#pragma unroll
        for (int j = 0; j < 4; j++)
            g_Op[half][row*DOUT + tx + j*16] = O[i][j];
    }
}

// ============================================================
// Combine the two split-K partials.
// ============================================================
__global__ __launch_bounds__(256) void combine_kernel(float* __restrict__ out)
{
    int idx = blockIdx.x * 256 + threadIdx.x;
    int row = idx >> 6;
    float m0 = g_m[0][row], m1 = g_m[1][row];
    float mx = fmaxf(m0, m1);
    float a0 = __expf(m0 - mx);
    float a1 = __expf(m1 - mx);
    float denom = g_l[0][row]*a0 + g_l[1][row]*a1;
    out[idx] = (g_Op[0][idx]*a0 + g_Op[1][idx]*a1) / denom;
}

// ============================================================
extern "C" void kernel_launch(void* const* d_in, const int* in_sizes, int n_in,
                              void* d_out, int out_size)
{
    const float* x  = (const float*)d_in[0];
    const float* Wq = (const float*)d_in[1];
    const float* Wk = (const float*)d_in[2];
    const float* Wv = (const float*)d_in[3];
    float* out = (float*)d_out;

    const int attn_smem = (BM*64 + BN*KSTR + BN*64 + BM*PSTR) * (int)sizeof(float);
    cudaFuncSetAttribute(attn_kernel, cudaFuncAttributeMaxDynamicSharedMemorySize, attn_smem);

    proj_kernel<<<dim3(SEQ/64, 3), dim3(16, 16)>>>(x, Wq, Wk, Wv);
    attn_kernel<<<dim3(SEQ/BM, 2), dim3(16, 16), attn_smem>>>();
    combine_kernel<<<(SEQ*DOUT)/256, 256>>>(out);
}

// round 4
// speedup vs baseline: 2.7601x; 2.7525x over previous
#include <cuda_runtime.h>
#include <cuda_bf16.h>
#include <cstdint>

#define SEQ  8192
#define DIN  512
#define DOUT 64

#define NSPLIT 2
#define KEYS_PER_SPLIT (SEQ / NSPLIT)
#define BM 128
#define BN 64
#define NTILES (KEYS_PER_SPLIT / BN)   // 64

// ---------------- device scratch (no allocations allowed) ----------------
__device__ __align__(16) __nv_bfloat16 g_Qhi[SEQ*DOUT];
__device__ __align__(16) __nv_bfloat16 g_Qlo[SEQ*DOUT];
__device__ __align__(16) __nv_bfloat16 g_Khi[SEQ*DOUT];
__device__ __align__(16) __nv_bfloat16 g_Klo[SEQ*DOUT];
__device__ __align__(16) __nv_bfloat16 g_Vhi[SEQ*DOUT];
__device__ __align__(16) __nv_bfloat16 g_Vlo[SEQ*DOUT];
__device__ float g_Op[NSPLIT][SEQ*DOUT];
__device__ float g_m[NSPLIT][SEQ];
__device__ float g_l[NSPLIT][SEQ];

// ---------------- small helpers ----------------
__device__ __forceinline__ uint32_t smem_u32(const void* p) {
    return (uint32_t)__cvta_generic_to_shared((void*)p);
}

// split (p0,p1) into packed bf16x2 hi + bf16x2 lo (residual)
__device__ __forceinline__ void split2(float p0, float p1, uint32_t& h, uint32_t& l) {
    uint32_t hh;
    asm("cvt.rn.bf16x2.f32 %0, %1, %2;" : "=r"(hh) : "f"(p1), "f"(p0));
    float f0 = __uint_as_float(hh << 16);
    float f1 = __uint_as_float(hh & 0xFFFF0000u);
    uint32_t ll;
    float r0 = p0 - f0, r1 = p1 - f1;
    asm("cvt.rn.bf16x2.f32 %0, %1, %2;" : "=r"(ll) : "f"(r1), "f"(r0));
    h = hh; l = ll;
}

__device__ __forceinline__ void mma16816(float c[4], const uint32_t a[4],
                                         uint32_t b0, uint32_t b1) {
    asm volatile("mma.sync.aligned.m16n8k16.row.col.f32.bf16.bf16.f32 "
        "{%0,%1,%2,%3}, {%4,%5,%6,%7}, {%8,%9}, {%0,%1,%2,%3};"
        : "+f"(c[0]), "+f"(c[1]), "+f"(c[2]), "+f"(c[3])
        : "r"(a[0]), "r"(a[1]), "r"(a[2]), "r"(a[3]), "r"(b0), "r"(b1));
}
__device__ __forceinline__ void ldsm4(uint32_t r[4], uint32_t addr) {
    asm volatile("ldmatrix.sync.aligned.m8n8.x4.shared.b16 {%0,%1,%2,%3}, [%4];"
        : "=r"(r[0]), "=r"(r[1]), "=r"(r[2]), "=r"(r[3]) : "r"(addr));
}
__device__ __forceinline__ void ldsm4t(uint32_t r[4], uint32_t addr) {
    asm volatile("ldmatrix.sync.aligned.m8n8.x4.trans.shared.b16 {%0,%1,%2,%3}, [%4];"
        : "=r"(r[0]), "=r"(r[1]), "=r"(r[2]), "=r"(r[3]) : "r"(addr));
}

// ============================================================
// Projection: out = x @ W  (M=8192, N=64, K=512). Q scaled by 1/8.
// Epilogue writes split bf16 hi/lo directly (prep fused away).
// ============================================================
__global__ __launch_bounds__(256) void proj_kernel(
    const float* __restrict__ x,  const float* __restrict__ Wq,
    const float* __restrict__ Wk, const float* __restrict__ Wv)
{
    __shared__ float xs[64*64];
    __shared__ float ws[64*64];

    const int which = blockIdx.y;
    const float* W = (which == 0) ? Wq : ((which == 1) ? Wk : Wv);
    __nv_bfloat16* hiArr = (which == 0) ? g_Qhi : ((which == 1) ? g_Khi : g_Vhi);
    __nv_bfloat16* loArr = (which == 0) ? g_Qlo : ((which == 1) ? g_Klo : g_Vlo);
    const float scale = (which == 0) ? 0.125f : 1.0f;

    const int row0 = blockIdx.x * 64;
    const int tx = threadIdx.x, ty = threadIdx.y;
    const int tid = ty * 16 + tx;

    float acc[4][4];
#pragma unroll
    for (int i = 0; i < 4; i++)
#pragma unroll
        for (int j = 0; j < 4; j++) acc[i][j] = 0.0f;

    for (int kt = 0; kt < 8; kt++) {
#pragma unroll
        for (int i = 0; i < 4; i++) {
            int lin = tid + 256 * i;
            int r = lin >> 4, c = (lin & 15) * 4;
            *(float4*)&xs[r*64 + c] = *(const float4*)&x[(row0 + r)*DIN + kt*64 + c];
            *(float4*)&ws[r*64 + c] = *(const float4*)&W[(kt*64 + r)*DOUT + c];
        }
        __syncthreads();
#pragma unroll 4
        for (int k = 0; k < 64; k += 4) {
            float4 a[4], b[4];
#pragma unroll
            for (int i = 0; i < 4; i++) a[i] = *(float4*)&xs[(ty*4 + i)*64 + k];
#pragma unroll
            for (int t = 0; t < 4; t++) b[t] = *(float4*)&ws[(k + t)*64 + tx*4];
#pragma unroll
            for (int i = 0; i < 4; i++) {
                acc[i][0] = fmaf(a[i].x,b[0].x, fmaf(a[i].y,b[1].x, fmaf(a[i].z,b[2].x, fmaf(a[i].w,b[3].x, acc[i][0]))));
                acc[i][1] = fmaf(a[i].x,b[0].y, fmaf(a[i].y,b[1].y, fmaf(a[i].z,b[2].y, fmaf(a[i].w,b[3].y, acc[i][1]))));
                acc[i][2] = fmaf(a[i].x,b[0].z, fmaf(a[i].y,b[1].z, fmaf(a[i].z,b[2].z, fmaf(a[i].w,b[3].z, acc[i][2]))));
                acc[i][3] = fmaf(a[i].x,b[0].w, fmaf(a[i].y,b[1].w, fmaf(a[i].z,b[2].w, fmaf(a[i].w,b[3].w, acc[i][3]))));
            }
        }
        __syncthreads();
    }
#pragma unroll
    for (int i = 0; i < 4; i++) {
        float v0 = acc[i][0]*scale, v1 = acc[i][1]*scale;
        float v2 = acc[i][2]*scale, v3 = acc[i][3]*scale;
        uint32_t h01, l01, h23, l23;
        split2(v0, v1, h01, l01);
        split2(v2, v3, h23, l23);
        const int row = row0 + ty*4 + i;
        *(uint2*)&hiArr[row*DOUT + tx*4] = make_uint2(h01, h23);
        *(uint2*)&loArr[row*DOUT + tx*4] = make_uint2(l01, l23);
    }
}

// ============================================================
// HMMA flash attention (split-bf16 3-pass), cp.async double-buffered.
// smem stage (32KB): KHI 0, KLO 8192, VHI 16384, VLO 24576; rows 128B,
// 16B-chunk xor-swizzle: chunk c of row r stored at (c ^ (r&7)).
// ============================================================
__device__ __forceinline__ void issue_tile_load(uint32_t smb, int stage, int kb, int tid) {
#pragma unroll
    for (int j = 0; j < 8; j++) {
        int i = tid + 256 * j;          // 0..2047
        int sel = i >> 9;               // 0 khi, 1 klo, 2 vhi, 3 vlo
        int r = (i >> 3) & 63;
        int c = i & 7;
        const __nv_bfloat16* base = (sel == 0) ? g_Khi : (sel == 1) ? g_Klo
                                  : (sel == 2) ? g_Vhi : g_Vlo;
        const __nv_bfloat16* src = base + (kb + r) * DOUT + c * 8;
        uint32_t dst = smb + stage * 32768 + sel * 8192 + r * 128 + ((c ^ (r & 7)) << 4);
        unsigned long long g = (unsigned long long)__cvta_generic_to_global((void*)src);
        asm volatile("cp.async.cg.shared.global [%0], [%1], 16;" :: "r"(dst), "l"(g) : "memory");
    }
}

__global__ __launch_bounds__(256, 1) void attn_kernel()
{
    extern __shared__ char sm[];
    const uint32_t smb = smem_u32(sm);
    const int tid  = threadIdx.x;
    const int lane = tid & 31;
    const int wid  = tid >> 5;
    const int gid  = lane >> 2;     // row group within fragment
    const int m4   = lane & 3;      // col pair within fragment
    const int row0 = blockIdx.x * BM;
    const int split = blockIdx.y;
    const int kb0  = split * KEYS_PER_SPLIT;
    const int q0   = row0 + wid * 16;

    // ---- persistent Q fragments (hi/lo), straight from gmem ----
    uint32_t qhi[4][4], qlo[4][4];
#pragma unroll
    for (int kc = 0; kc < 4; kc++) {
        const int base = (q0 + gid) * DOUT + kc * 16 + m4 * 2;
        qhi[kc][0] = *(const uint32_t*)&g_Qhi[base];
        qhi[kc][1] = *(const uint32_t*)&g_Qhi[base + 8*DOUT];
        qhi[kc][2] = *(const uint32_t*)&g_Qhi[base + 8];
        qhi[kc][3] = *(const uint32_t*)&g_Qhi[base + 8*DOUT + 8];
        qlo[kc][0] = *(const uint32_t*)&g_Qlo[base];
        qlo[kc][1] = *(const uint32_t*)&g_Qlo[base + 8*DOUT];
        qlo[kc][2] = *(const uint32_t*)&g_Qlo[base + 8];
        qlo[kc][3] = *(const uint32_t*)&g_Qlo[base + 8*DOUT + 8];
    }

    float O[8][4];
#pragma unroll
    for (int nt = 0; nt < 8; nt++)
#pragma unroll
        for (int c = 0; c < 4; c++) O[nt][c] = 0.0f;
    float mrow[2] = {-1e30f, -1e30f};
    float lrow[2] = {0.0f, 0.0f};

    issue_tile_load(smb, 0, kb0, tid);
    asm volatile("cp.async.commit_group;" ::: "memory");

    for (int t = 0; t < NTILES; t++) {
        if (t + 1 < NTILES) {
            issue_tile_load(smb, (t + 1) & 1, kb0 + (t + 1) * BN, tid);
            asm volatile("cp.async.commit_group;" ::: "memory");
            asm volatile("cp.async.wait_group 1;" ::: "memory");
        } else {
            asm volatile("cp.async.wait_group 0;" ::: "memory");
        }
        __syncthreads();

        const uint32_t bK = smb + (t & 1) * 32768;
        const uint32_t bV = bK + 16384;

        // ---- S = Q @ K^T (3 split passes), fp32 accum ----
        float S[8][4];
#pragma unroll
        for (int nt = 0; nt < 8; nt++)
#pragma unroll
            for (int c = 0; c < 4; c++) S[nt][c] = 0.0f;

#pragma unroll
        for (int kc = 0; kc < 4; kc++) {
            uint32_t bh[4][4], bl[4][4];
#pragma unroll
            for (int p = 0; p < 4; p++) {
                int key = p * 16 + (lane & 7) + ((lane >> 4) & 1) * 8;
                int ch  = kc * 2 + ((lane >> 3) & 1);
                uint32_t ad = bK + key * 128 + ((ch ^ (key & 7)) << 4);
                ldsm4(bh[p], ad);
                ldsm4(bl[p], ad + 8192);
            }
#pragma unroll
            for (int nt = 0; nt < 8; nt++) {
                int p = nt >> 1, o = (nt & 1) * 2;
                mma16816(S[nt], qhi[kc], bh[p][o], bh[p][o+1]);
                mma16816(S[nt], qhi[kc], bl[p][o], bl[p][o+1]);
                mma16816(S[nt], qlo[kc], bh[p][o], bh[p][o+1]);
            }
        }

        // ---- online softmax (rows fully warp-local) ----
#pragma unroll
        for (int h = 0; h < 2; h++) {
            float mx = -1e30f;
#pragma unroll
            for (int nt = 0; nt < 8; nt++)
                mx = fmaxf(mx, fmaxf(S[nt][2*h], S[nt][2*h+1]));
            mx = fmaxf(mx, __shfl_xor_sync(0xFFFFFFFFu, mx, 1));
            mx = fmaxf(mx, __shfl_xor_sync(0xFFFFFFFFu, mx, 2));
            if (mx > mrow[h]) {
                float alpha = __expf(mrow[h] - mx);
                lrow[h] *= alpha;
#pragma unroll
                for (int nt = 0; nt < 8; nt++) { O[nt][2*h] *= alpha; O[nt][2*h+1] *= alpha; }
                mrow[h] = mx;
            }
            float sum = 0.0f;
#pragma unroll
            for (int nt = 0; nt < 8; nt++) {
                float p0 = __expf(S[nt][2*h]   - mrow[h]);
                float p1 = __expf(S[nt][2*h+1] - mrow[h]);
                S[nt][2*h] = p0; S[nt][2*h+1] = p1;
                sum += p0 + p1;
            }
            lrow[h] += sum;     // per-lane partial; quad-reduced in epilogue
        }

        // ---- O += P @ V (3 split passes) ----
#pragma unroll
        for (int kc = 0; kc < 4; kc++) {
            uint32_t ah[4], al[4];
            split2(S[2*kc][0],   S[2*kc][1],   ah[0], al[0]);
            split2(S[2*kc][2],   S[2*kc][3],   ah[1], al[1]);
            split2(S[2*kc+1][0], S[2*kc+1][1], ah[2], al[2]);
            split2(S[2*kc+1][2], S[2*kc+1][3], ah[3], al[3]);
            uint32_t vh[4][4], vl[4][4];
#pragma unroll
            for (int p = 0; p < 4; p++) {
                int key = kc * 16 + (lane & 7) + ((lane >> 3) & 1) * 8;
                int ch  = 2 * p + ((lane >> 4) & 1);
                uint32_t ad = bV + key * 128 + ((ch ^ (key & 7)) << 4);
                ldsm4t(vh[p], ad);
                ldsm4t(vl[p], ad + 8192);
            }
#pragma unroll
            for (int nt = 0; nt < 8; nt++) {
                int p = nt >> 1, o = (nt & 1) * 2;
                mma16816(O[nt], ah, vh[p][o], vh[p][o+1]);
                mma16816(O[nt], ah, vl[p][o], vl[p][o+1]);
                mma16816(O[nt], al, vh[p][o], vh[p][o+1]);
            }
        }
        __syncthreads();
    }

    // ---- epilogue: reduce l across quad, write unnormalized partials ----
#pragma unroll
    for (int h = 0; h < 2; h++) {
        float l = lrow[h];
        l += __shfl_xor_sync(0xFFFFFFFFu, l, 1);
        l += __shfl_xor_sync(0xFFFFFFFFu, l, 2);
        const int r = q0 + gid + h * 8;
        if (m4 == 0) { g_m[split][r] = mrow[h]; g_l[split][r] = l; }
#pragma unroll
        for (int nt = 0; nt < 8; nt++) {
            float2 v = make_float2(O[nt][2*h], O[nt][2*h+1]);
            *(float2*)&g_Op[split][r*DOUT + nt*8 + m4*2] = v;
        }
    }
}

// ============================================================
// Combine the 2 split-K partials.
// ============================================================
__global__ __launch_bounds__(256) void combine_kernel(float* __restrict__ out)
{
    int idx = blockIdx.x * 256 + threadIdx.x;
    int row = idx >> 6;
    float m0 = g_m[0][row], m1 = g_m[1][row];
    float mx = fmaxf(m0, m1);
    float a0 = __expf(m0 - mx);
    float a1 = __expf(m1 - mx);
    float denom = g_l[0][row]*a0 + g_l[1][row]*a1;
    out[idx] = (g_Op[0][idx]*a0 + g_Op[1][idx]*a1) / denom;
}

// ============================================================
extern "C" void kernel_launch(void* const* d_in, const int* in_sizes, int n_in,
                              void* d_out, int out_size)
{
    (void)in_sizes; (void)n_in; (void)out_size;
    const float* x  = (const float*)d_in[0];
    const float* Wq = (const float*)d_in[1];
    const float* Wk = (const float*)d_in[2];
    const float* Wv = (const float*)d_in[3];
    float* out = (float*)d_out;

    const int attn_smem = 2 * 32768;
    cudaFuncSetAttribute(attn_kernel, cudaFuncAttributeMaxDynamicSharedMemorySize, attn_smem);

    proj_kernel<<<dim3(SEQ/64, 3), dim3(16, 16)>>>(x, Wq, Wk, Wv);
    attn_kernel<<<dim3(SEQ/BM, NSPLIT), 256, attn_smem>>>();
    combine_kernel<<<(SEQ*DOUT)/256, 256>>>(out);
}

// round 6
// speedup vs baseline: 3.2271x; 1.1692x over previous
#include <cuda_runtime.h>
#include <cuda_bf16.h>
#include <cstdint>

#define SEQ  8192
#define DIN  512
#define DOUT 64

#define NSPLIT 2
#define KEYS_PER_SPLIT (SEQ / NSPLIT)
#define BM 128
#define BN 64
#define NTILES (KEYS_PER_SPLIT / BN)   // 64

// ---------------- device scratch (no allocations allowed) ----------------
__device__ __align__(16) __nv_bfloat16 g_Qhi[SEQ*DOUT];
__device__ __align__(16) __nv_bfloat16 g_Qlo[SEQ*DOUT];
__device__ __align__(16) __nv_bfloat16 g_Khi[SEQ*DOUT];
__device__ __align__(16) __nv_bfloat16 g_Klo[SEQ*DOUT];
__device__ __align__(16) __nv_bfloat16 g_Vhi[SEQ*DOUT];
__device__ __align__(16) __nv_bfloat16 g_Vlo[SEQ*DOUT];
__device__ float g_Op[NSPLIT][SEQ*DOUT];
__device__ float g_m[NSPLIT][SEQ];
__device__ float g_l[NSPLIT][SEQ];

// ---------------- small helpers ----------------
__device__ __forceinline__ uint32_t smem_u32(const void* p) {
    return (uint32_t)__cvta_generic_to_shared((void*)p);
}
__device__ __forceinline__ float fexp2(float x) {
    float y;
    asm("ex2.approx.f32 %0, %1;" : "=f"(y) : "f"(x));
    return y;
}

// split (p0,p1) into packed bf16x2 hi + bf16x2 lo (residual)
__device__ __forceinline__ void split2(float p0, float p1, uint32_t& h, uint32_t& l) {
    uint32_t hh;
    asm("cvt.rn.bf16x2.f32 %0, %1, %2;" : "=r"(hh) : "f"(p1), "f"(p0));
    float f0 = __uint_as_float(hh << 16);
    float f1 = __uint_as_float(hh & 0xFFFF0000u);
    uint32_t ll;
    float r0 = p0 - f0, r1 = p1 - f1;
    asm("cvt.rn.bf16x2.f32 %0, %1, %2;" : "=r"(ll) : "f"(r1), "f"(r0));
    h = hh; l = ll;
}

__device__ __forceinline__ void mma16816(float c[4], const uint32_t a[4],
                                         uint32_t b0, uint32_t b1) {
    asm volatile("mma.sync.aligned.m16n8k16.row.col.f32.bf16.bf16.f32 "
        "{%0,%1,%2,%3}, {%4,%5,%6,%7}, {%8,%9}, {%0,%1,%2,%3};"
        : "+f"(c[0]), "+f"(c[1]), "+f"(c[2]), "+f"(c[3])
        : "r"(a[0]), "r"(a[1]), "r"(a[2]), "r"(a[3]), "r"(b0), "r"(b1));
}
__device__ __forceinline__ void ldsm4(uint32_t r[4], uint32_t addr) {
    asm volatile("ldmatrix.sync.aligned.m8n8.x4.shared.b16 {%0,%1,%2,%3}, [%4];"
        : "=r"(r[0]), "=r"(r[1]), "=r"(r[2]), "=r"(r[3]) : "r"(addr));
}
__device__ __forceinline__ void ldsm4t(uint32_t r[4], uint32_t addr) {
    asm volatile("ldmatrix.sync.aligned.m8n8.x4.trans.shared.b16 {%0,%1,%2,%3}, [%4];"
        : "=r"(r[0]), "=r"(r[1]), "=r"(r[2]), "=r"(r[3]) : "r"(addr));
}

// ============================================================
// Projection via HMMA split-bf16 (3 passes): out = x @ W.
// M=8192 (BM=128/CTA), N=64, K=512 streamed in 64-chunks.
// Q gets 0.125*log2(e) folded in (base-2 softmax downstream).
// smem: XHI [128][64]bf16 @0, XLO @16K, WHI [64][64]bf16 @32K, WLO @40K.
// Rows are 128B; 16B chunk c of row r stored at (c ^ (r&7)).
// ============================================================
#define PJ_XHI 0
#define PJ_XLO 16384
#define PJ_WHI 32768
#define PJ_WLO 40960

__global__ __launch_bounds__(256, 2) void proj_kernel(
    const float* __restrict__ x,  const float* __restrict__ Wq,
    const float* __restrict__ Wk, const float* __restrict__ Wv)
{
    __shared__ __align__(16) char sm[49152];
    const uint32_t smb = smem_u32(sm);

    const int which = blockIdx.y;
    const float* W = (which == 0) ? Wq : ((which == 1) ? Wk : Wv);
    __nv_bfloat16* hiArr = (which == 0) ? g_Qhi : ((which == 1) ? g_Khi : g_Vhi);
    __nv_bfloat16* loArr = (which == 0) ? g_Qlo : ((which == 1) ? g_Klo : g_Vlo);
    // Q: 1/sqrt(64) * log2(e) so scores are in log2 domain
    const float scale = (which == 0) ? 0.18033688011112042f : 1.0f;

    const int row0 = blockIdx.x * BM;
    const int tid  = threadIdx.x;
    const int lane = tid & 31;
    const int wid  = tid >> 5;
    const int wm   = wid * 16;

    float C[8][4];
#pragma unroll
    for (int nt = 0; nt < 8; nt++)
#pragma unroll
        for (int c = 0; c < 4; c++) C[nt][c] = 0.0f;

    for (int kt = 0; kt < 8; kt++) {
        __syncthreads();   // prior MMA reads of smem complete
        // ---- load + convert x chunk [128 rows x 64 k] ----
#pragma unroll
        for (int j = 0; j < 4; j++) {
            int i = tid + 256 * j;        // 16B-chunk index 0..1023
            int r = i >> 3, c = i & 7;
            const float* src = x + (row0 + r) * DIN + kt * 64 + c * 8;
            float4 a = *(const float4*)src;
            float4 b = *(const float4*)(src + 4);
            uint32_t h0,l0,h1,l1,h2,l2,h3,l3;
            split2(a.x, a.y, h0, l0);
            split2(a.z, a.w, h1, l1);
            split2(b.x, b.y, h2, l2);
            split2(b.z, b.w, h3, l3);
            int off = r * 128 + ((c ^ (r & 7)) << 4);
            *(uint4*)(sm + PJ_XHI + off) = make_uint4(h0, h1, h2, h3);
            *(uint4*)(sm + PJ_XLO + off) = make_uint4(l0, l1, l2, l3);
        }
        // ---- load + convert W chunk [64 k x 64 n] ----
#pragma unroll
        for (int j = 0; j < 2; j++) {
            int i = tid + 256 * j;        // 0..511
            int r = i >> 3, c = i & 7;
            const float* src = W + (kt * 64 + r) * DOUT + c * 8;
            float4 a = *(const float4*)src;
            float4 b = *(const float4*)(src + 4);
            uint32_t h0,l0,h1,l1,h2,l2,h3,l3;
            split2(a.x, a.y, h0, l0);
            split2(a.z, a.w, h1, l1);
            split2(b.x, b.y, h2, l2);
            split2(b.z, b.w, h3, l3);
            int off = r * 128 + ((c ^ (r & 7)) << 4);
            *(uint4*)(sm + PJ_WHI + off) = make_uint4(h0, h1, h2, h3);
            *(uint4*)(sm + PJ_WLO + off) = make_uint4(l0, l1, l2, l3);
        }
        __syncthreads();

#pragma unroll
        for (int kc = 0; kc < 4; kc++) {
            // A fragments (x): rows wm..wm+15, k16 block kc
            int arow = wm + (lane & 7) + ((lane >> 3) & 1) * 8;
            int ach  = kc * 2 + (lane >> 4);
            uint32_t ad = smb + PJ_XHI + arow * 128 + ((ach ^ (arow & 7)) << 4);
            uint32_t ah[4], al[4];
            ldsm4(ah, ad);
            ldsm4(al, ad + 16384);
            // B fragments (W): k rows kc*16.., n 16-blocks p
            uint32_t bh[4][4], bl[4][4];
            int krow = kc * 16 + (lane & 7) + ((lane >> 3) & 1) * 8;
#pragma unroll
            for (int p = 0; p < 4; p++) {
                int ch = 2 * p + (lane >> 4);
                uint32_t bd = smb + PJ_WHI + krow * 128 + ((ch ^ (krow & 7)) << 4);
                ldsm4t(bh[p], bd);
                ldsm4t(bl[p], bd + 8192);
            }
#pragma unroll
            for (int nt = 0; nt < 8; nt++) {
                int p = nt >> 1, o = (nt & 1) * 2;
                mma16816(C[nt], ah, bh[p][o], bh[p][o+1]);
                mma16816(C[nt], ah, bl[p][o], bl[p][o+1]);
                mma16816(C[nt], al, bh[p][o], bh[p][o+1]);
            }
        }
    }

    // ---- epilogue: scale, split to bf16 hi/lo, store ----
    const int gid = lane >> 2, m4 = lane & 3;
#pragma unroll
    for (int nt = 0; nt < 8; nt++) {
        uint32_t h, l;
        const int row = row0 + wm + gid;
        const int col = nt * 8 + m4 * 2;
        split2(C[nt][0] * scale, C[nt][1] * scale, h, l);
        *(uint32_t*)&hiArr[row * DOUT + col] = h;
        *(uint32_t*)&loArr[row * DOUT + col] = l;
        split2(C[nt][2] * scale, C[nt][3] * scale, h, l);
        *(uint32_t*)&hiArr[(row + 8) * DOUT + col] = h;
        *(uint32_t*)&loArr[(row + 8) * DOUT + col] = l;
    }
}

// ============================================================
// HMMA flash attention (split-bf16 3-pass), cp.async double-buffered.
// Scores arrive in log2 domain (log2e folded into Q) -> ex2 softmax.
// smem stage (32KB): KHI 0, KLO 8192, VHI 16384, VLO 24576; rows 128B,
// 16B-chunk xor-swizzle: chunk c of row r stored at (c ^ (r&7)).
// ============================================================
__device__ __forceinline__ void issue_tile_load(uint32_t smb, int stage, int kb, int tid) {
#pragma unroll
    for (int j = 0; j < 8; j++) {
        int i = tid + 256 * j;          // 0..2047
        int sel = i >> 9;               // 0 khi, 1 klo, 2 vhi, 3 vlo
        int r = (i >> 3) & 63;
        int c = i & 7;
        const __nv_bfloat16* base = (sel == 0) ? g_Khi : (sel == 1) ? g_Klo
                                  : (sel == 2) ? g_Vhi : g_Vlo;
        const __nv_bfloat16* src = base + (kb + r) * DOUT + c * 8;
        uint32_t dst = smb + stage * 32768 + sel * 8192 + r * 128 + ((c ^ (r & 7)) << 4);
        unsigned long long g = (unsigned long long)__cvta_generic_to_global((void*)src);
        asm volatile("cp.async.cg.shared.global [%0], [%1], 16;" :: "r"(dst), "l"(g) : "memory");
    }
}

__global__ __launch_bounds__(256, 1) void attn_kernel()
{
    extern __shared__ char sm[];
    const uint32_t smb = smem_u32(sm);
    const int tid  = threadIdx.x;
    const int lane = tid & 31;
    const int wid  = tid >> 5;
    const int gid  = lane >> 2;     // row group within fragment
    const int m4   = lane & 3;      // col pair within fragment
    const int row0 = blockIdx.x * BM;
    const int split = blockIdx.y;
    const int kb0  = split * KEYS_PER_SPLIT;
    const int q0   = row0 + wid * 16;

    // ---- persistent Q fragments (hi/lo), straight from gmem ----
    uint32_t qhi[4][4], qlo[4][4];
#pragma unroll
    for (int kc = 0; kc < 4; kc++) {
        const int base = (q0 + gid) * DOUT + kc * 16 + m4 * 2;
        qhi[kc][0] = *(const uint32_t*)&g_Qhi[base];
        qhi[kc][1] = *(const uint32_t*)&g_Qhi[base + 8*DOUT];
        qhi[kc][2] = *(const uint32_t*)&g_Qhi[base + 8];
        qhi[kc][3] = *(const uint32_t*)&g_Qhi[base + 8*DOUT + 8];
        qlo[kc][0] = *(const uint32_t*)&g_Qlo[base];
        qlo[kc][1] = *(const uint32_t*)&g_Qlo[base + 8*DOUT];
        qlo[kc][2] = *(const uint32_t*)&g_Qlo[base + 8];
        qlo[kc][3] = *(const uint32_t*)&g_Qlo[base + 8*DOUT + 8];
    }

    float O[8][4];
#pragma unroll
    for (int nt = 0; nt < 8; nt++)
#pragma unroll
        for (int c = 0; c < 4; c++) O[nt][c] = 0.0f;
    float mrow[2] = {-1e30f, -1e30f};
    float lrow[2] = {0.0f, 0.0f};

    issue_tile_load(smb, 0, kb0, tid);
    asm volatile("cp.async.commit_group;" ::: "memory");

    for (int t = 0; t < NTILES; t++) {
        if (t + 1 < NTILES) {
            issue_tile_load(smb, (t + 1) & 1, kb0 + (t + 1) * BN, tid);
            asm volatile("cp.async.commit_group;" ::: "memory");
            asm volatile("cp.async.wait_group 1;" ::: "memory");
        } else {
            asm volatile("cp.async.wait_group 0;" ::: "memory");
        }
        __syncthreads();

        const uint32_t bK = smb + (t & 1) * 32768;
        const uint32_t bV = bK + 16384;

        // ---- S = Q @ K^T (3 split passes), fp32 accum, log2 domain ----
        float S[8][4];
#pragma unroll
        for (int nt = 0; nt < 8; nt++)
#pragma unroll
            for (int c = 0; c < 4; c++) S[nt][c] = 0.0f;

#pragma unroll
        for (int kc = 0; kc < 4; kc++) {
            uint32_t bh[4][4], bl[4][4];
#pragma unroll
            for (int p = 0; p < 4; p++) {
                int key = p * 16 + (lane & 7) + ((lane >> 4) & 1) * 8;
                int ch  = kc * 2 + ((lane >> 3) & 1);
                uint32_t ad = bK + key * 128 + ((ch ^ (key & 7)) << 4);
                ldsm4(bh[p], ad);
                ldsm4(bl[p], ad + 8192);
            }
#pragma unroll
            for (int nt = 0; nt < 8; nt++) {
                int p = nt >> 1, o = (nt & 1) * 2;
                mma16816(S[nt], qhi[kc], bh[p][o], bh[p][o+1]);
                mma16816(S[nt], qhi[kc], bl[p][o], bl[p][o+1]);
                mma16816(S[nt], qlo[kc], bh[p][o], bh[p][o+1]);
            }
        }

        // ---- online softmax, base 2 (rows fully warp-local) ----
#pragma unroll
        for (int h = 0; h < 2; h++) {
            float mx = -1e30f;
#pragma unroll
            for (int nt = 0; nt < 8; nt++)
                mx = fmaxf(mx, fmaxf(S[nt][2*h], S[nt][2*h+1]));
            mx = fmaxf(mx, __shfl_xor_sync(0xFFFFFFFFu, mx, 1));
            mx = fmaxf(mx, __shfl_xor_sync(0xFFFFFFFFu, mx, 2));
            float mn = fmaxf(mrow[h], mx);
            float alpha = fexp2(mrow[h] - mn);
            mrow[h] = mn;
            lrow[h] *= alpha;
#pragma unroll
            for (int nt = 0; nt < 8; nt++) { O[nt][2*h] *= alpha; O[nt][2*h+1] *= alpha; }
            float sum = 0.0f;
#pragma unroll
            for (int nt = 0; nt < 8; nt++) {
                float p0 = fexp2(S[nt][2*h]   - mn);
                float p1 = fexp2(S[nt][2*h+1] - mn);
                S[nt][2*h] = p0; S[nt][2*h+1] = p1;
                sum += p0 + p1;
            }
            lrow[h] += sum;     // per-lane partial; quad-reduced in epilogue
        }

        // ---- O += P @ V (3 split passes) ----
#pragma unroll
        for (int kc = 0; kc < 4; kc++) {
            uint32_t ah[4], al[4];
            split2(S[2*kc][0],   S[2*kc][1],   ah[0], al[0]);
            split2(S[2*kc][2],   S[2*kc][3],   ah[1], al[1]);
            split2(S[2*kc+1][0], S[2*kc+1][1], ah[2], al[2]);
            split2(S[2*kc+1][2], S[2*kc+1][3], ah[3], al[3]);
            uint32_t vh[4][4], vl[4][4];
#pragma unroll
            for (int p = 0; p < 4; p++) {
                int key = kc * 16 + (lane & 7) + ((lane >> 3) & 1) * 8;
                int ch  = 2 * p + ((lane >> 4) & 1);
                uint32_t ad = bV + key * 128 + ((ch ^ (key & 7)) << 4);
                ldsm4t(vh[p], ad);
                ldsm4t(vl[p], ad + 8192);
            }
#pragma unroll
            for (int nt = 0; nt < 8; nt++) {
                int p = nt >> 1, o = (nt & 1) * 2;
                mma16816(O[nt], ah, vh[p][o], vh[p][o+1]);
                mma16816(O[nt], ah, vl[p][o], vl[p][o+1]);
                mma16816(O[nt], al, vh[p][o], vh[p][o+1]);
            }
        }
        __syncthreads();
    }

    // ---- epilogue: reduce l across quad, write unnormalized partials ----
#pragma unroll
    for (int h = 0; h < 2; h++) {
        float l = lrow[h];
        l += __shfl_xor_sync(0xFFFFFFFFu, l, 1);
        l += __shfl_xor_sync(0xFFFFFFFFu, l, 2);
        const int r = q0 + gid + h * 8;
        if (m4 == 0) { g_m[split][r] = mrow[h]; g_l[split][r] = l; }
#pragma unroll
        for (int nt = 0; nt < 8; nt++) {
            float2 v = make_float2(O[nt][2*h], O[nt][2*h+1]);
            *(float2*)&g_Op[split][r*DOUT + nt*8 + m4*2] = v;
        }
    }
}

// ============================================================
// Combine the 2 split-K partials (m is in log2 domain).
// ============================================================
__global__ __launch_bounds__(256) void combine_kernel(float* __restrict__ out)
{
    int idx = blockIdx.x * 256 + threadIdx.x;
    int row = idx >> 6;
    float m0 = g_m[0][row], m1 = g_m[1][row];
    float mx = fmaxf(m0, m1);
    float a0 = fexp2(m0 - mx);
    float a1 = fexp2(m1 - mx);
    float denom = g_l[0][row]*a0 + g_l[1][row]*a1;
    out[idx] = (g_Op[0][idx]*a0 + g_Op[1][idx]*a1) / denom;
}

// ============================================================
extern "C" void kernel_launch(void* const* d_in, const int* in_sizes, int n_in,
                              void* d_out, int out_size)
{
    (void)in_sizes; (void)n_in; (void)out_size;
    const float* x  = (const float*)d_in[0];
    const float* Wq = (const float*)d_in[1];
    const float* Wk = (const float*)d_in[2];
    const float* Wv = (const float*)d_in[3];
    float* out = (float*)d_out;

    const int attn_smem = 2 * 32768;
    cudaFuncSetAttribute(attn_kernel, cudaFuncAttributeMaxDynamicSharedMemorySize, attn_smem);

    proj_kernel<<<dim3(SEQ/BM, 3), 256>>>(x, Wq, Wk, Wv);
    attn_kernel<<<dim3(SEQ/BM, NSPLIT), 256, attn_smem>>>();
    combine_kernel<<<(SEQ*DOUT)/256, 256>>>(out);
}